// round 5
// baseline (speedup 1.0000x reference)
#include <cuda_runtime.h>
#include <cstdint>

#define NN 50000
#define EE 400000
#define H1 256
#define H2 128

// ---- scratch layout (floats) ----
#define OFF_INC1   0                       // N*256
#define OFF_OUT1   12800000                // N*256
#define OFF_INC2   25600000                // N*128
#define OFF_OUT2   32000000                // N*128
#define OFF_E1SUM  38400000                // 256
#define OFF_E2SUM  38400256                // 128
#define OFF_N1SUM  38400384                // 256
#define OFF_N2SUM  38400640                // 128
#define OFF_INVIN  38400768                // N
#define OFF_INVOUT 38450768                // N
#define SCR_TOTAL  38500864
#define ZERO_FLOATS 38400768               // [0, OFF_INVIN) must be zeroed

__device__ float g_scr[SCR_TOTAL];
__device__ int   g_cnt[2 * NN];

typedef unsigned long long ull;

__device__ __forceinline__ void red4(float* p, float a, float b, float c, float d) {
    asm volatile("red.global.add.v4.f32 [%0], {%1,%2,%3,%4};"
                 :: "l"(p), "f"(a), "f"(b), "f"(c), "f"(d) : "memory");
}
__device__ __forceinline__ ull pk2(float x) {
    ull r; asm("mov.b64 %0, {%1, %1};" : "=l"(r) : "f"(x)); return r;
}
__device__ __forceinline__ void ffma2(ull& acc, ull a, ull b) {
    asm("fma.rn.f32x2 %0, %1, %2, %0;" : "+l"(acc) : "l"(a), "l"(b));
}
__device__ __forceinline__ float2 up2(ull v) {
    float2 f; asm("mov.b64 {%0, %1}, %2;" : "=f"(f.x), "=f"(f.y) : "l"(v)); return f;
}

// ---------------- zero scratch ----------------
__global__ void k_zero() {
    long i = (long)blockIdx.x * 256 + threadIdx.x;
    if (i < ZERO_FLOATS / 4) {
        float4 z = {0.f, 0.f, 0.f, 0.f};
        *(float4*)(g_scr + i * 4) = z;
    }
    if (i < (2 * NN) / 4) {
        int4 z = {0, 0, 0, 0};
        *(int4*)(g_cnt + i * 4) = z;
    }
}

// ---------------- degrees ----------------
__global__ void k_deg(const int* __restrict__ snd, const int* __restrict__ rcv) {
    int i = blockIdx.x * 256 + threadIdx.x;
    if (i < EE) {
        atomicAdd(&g_cnt[rcv[i]], 1);
        atomicAdd(&g_cnt[NN + snd[i]], 1);
    }
}

__global__ void k_inv() {
    int i = blockIdx.x * 256 + threadIdx.x;
    if (i < NN) {
        int ci = g_cnt[i];      g_scr[OFF_INVIN  + i] = 1.0f / (float)(ci > 1 ? ci : 1);
        int co = g_cnt[NN + i]; g_scr[OFF_INVOUT + i] = 1.0f / (float)(co > 1 ? co : 1);
    }
}

// ---------------- fused edge kernel (warp-autonomous) ----------------
// 512 threads = 16 warps. Each warp owns 8 edges per group:
//   rows warp-uniform -> all a-operand LDS are single-address broadcasts,
//   sX/sE1 slices warp-private -> no __syncthreads in the loop.
// Per thread: 8 edges x 4 cols. e1 scatter comes straight from registers.
#define GRPS 50000   /* EE / 8 */
__global__ void __launch_bounds__(512, 1) k_edges(
    const float* __restrict__ edges, const int* __restrict__ snd, const int* __restrict__ rcv,
    const float* __restrict__ We1, const float* __restrict__ be1,
    const float* __restrict__ We2, const float* __restrict__ be2,
    float* __restrict__ e2_out)
{
    extern __shared__ float sm[];
    float* sWe2 = sm;                 // 256*128 = 32768
    float* sWe1 = sWe2 + 32768;       // 16*256  = 4096
    float* sE1  = sWe1 + 4096;        // 16 warps * 8*128 = 16384
    float* sX   = sE1 + 16384;        // 16 warps * 8*16  = 2048
    float* sbe1 = sX + 2048;          // 256
    float* sbe2 = sbe1 + 256;         // 128

    const int tid = threadIdx.x;
    for (int i = tid; i < 32768; i += 512) sWe2[i] = We2[i];
    for (int i = tid; i < 4096;  i += 512) sWe1[i] = We1[i];
    if (tid < 256) sbe1[tid] = be1[tid];
    else if (tid < 384) sbe2[tid - 256] = be2[tid - 256];
    __syncthreads();

    const int wid  = tid >> 5;
    const int lane = tid & 31;
    float* myE1 = sE1 + wid * 1024;   // 8 rows x 128
    float* myX  = sX  + wid * 128;    // 8 rows x 16
    const int jj = lane * 4;

    float cs1[2][4] = {{0.f,0.f,0.f,0.f},{0.f,0.f,0.f,0.f}};
    float cs2[4] = {0.f,0.f,0.f,0.f};

    float* g_inc1 = g_scr + OFF_INC1;
    float* g_out1 = g_scr + OFF_OUT1;
    float* g_inc2 = g_scr + OFF_INC2;
    float* g_out2 = g_scr + OFF_OUT2;

    const int le = lane >> 2, lq = lane & 3;   // X fill mapping

    for (int grp = blockIdx.x * 16 + wid; grp < GRPS; grp += gridDim.x * 16) {
        const long base = (long)grp * 8;
        __syncwarp();   // myX/myE1 free of previous-group readers
        // ---- fill X (8 edges x 16) + indices in lanes ----
        *(float4*)(myX + le * 16 + lq * 4) =
            *(const float4*)(edges + (base + le) * 16 + lq * 4);
        int idxreg = 0;
        if (lane < 8)       idxreg = snd[base + lane];
        else if (lane < 16) idxreg = rcv[base + lane - 8];
        __syncwarp();

        ull acc2[8][2];
        #pragma unroll
        for (int i = 0; i < 8; i++) { acc2[i][0] = 0ull; acc2[i][1] = 0ull; }

        #pragma unroll
        for (int h = 0; h < 2; h++) {
            // ---- phase A: e1[:, h*128+jj .. +3] for all 8 rows ----
            ull accA[8][2];
            #pragma unroll
            for (int i = 0; i < 8; i++) { accA[i][0] = 0ull; accA[i][1] = 0ull; }
            #pragma unroll
            for (int k0 = 0; k0 < 16; k0 += 4) {
                ulonglong2 w0 = *(const ulonglong2*)(sWe1 + (k0 + 0) * 256 + h * 128 + jj);
                ulonglong2 w1 = *(const ulonglong2*)(sWe1 + (k0 + 1) * 256 + h * 128 + jj);
                ulonglong2 w2 = *(const ulonglong2*)(sWe1 + (k0 + 2) * 256 + h * 128 + jj);
                ulonglong2 w3 = *(const ulonglong2*)(sWe1 + (k0 + 3) * 256 + h * 128 + jj);
                #pragma unroll
                for (int i = 0; i < 8; i++) {
                    float4 a4 = *(const float4*)(myX + i * 16 + k0);
                    ull ax = pk2(a4.x), ay = pk2(a4.y), az = pk2(a4.z), aw = pk2(a4.w);
                    ffma2(accA[i][0], ax, w0.x); ffma2(accA[i][1], ax, w0.y);
                    ffma2(accA[i][0], ay, w1.x); ffma2(accA[i][1], ay, w1.y);
                    ffma2(accA[i][0], az, w2.x); ffma2(accA[i][1], az, w2.y);
                    ffma2(accA[i][0], aw, w3.x); ffma2(accA[i][1], aw, w3.y);
                }
            }
            // relu+bias -> store to myE1 + scatter from registers
            {
                float4 b = *(const float4*)(sbe1 + h * 128 + jj);
                #pragma unroll
                for (int i = 0; i < 8; i++) {
                    float2 t0 = up2(accA[i][0]), t1 = up2(accA[i][1]);
                    float4 r;
                    r.x = fmaxf(t0.x + b.x, 0.f); r.y = fmaxf(t0.y + b.y, 0.f);
                    r.z = fmaxf(t1.x + b.z, 0.f); r.w = fmaxf(t1.y + b.w, 0.f);
                    *(float4*)(myE1 + i * 128 + jj) = r;
                    cs1[h][0] += r.x; cs1[h][1] += r.y; cs1[h][2] += r.z; cs1[h][3] += r.w;
                    int rI = __shfl_sync(0xffffffffu, idxreg, 8 + i);
                    int sI = __shfl_sync(0xffffffffu, idxreg, i);
                    red4(g_inc1 + (long)rI * 256 + h * 128 + jj, r.x, r.y, r.z, r.w);
                    red4(g_out1 + (long)sI * 256 + h * 128 + jj, r.x, r.y, r.z, r.w);
                }
            }
            __syncwarp();   // myE1 complete before cross-lane reads

            // ---- phase B: acc2 += e1_half @ We2[h*128.., jj..jj+3] ----
            #pragma unroll 2
            for (int k0 = 0; k0 < 128; k0 += 4) {
                ulonglong2 w0 = *(const ulonglong2*)(sWe2 + (h * 128 + k0 + 0) * 128 + jj);
                ulonglong2 w1 = *(const ulonglong2*)(sWe2 + (h * 128 + k0 + 1) * 128 + jj);
                ulonglong2 w2 = *(const ulonglong2*)(sWe2 + (h * 128 + k0 + 2) * 128 + jj);
                ulonglong2 w3 = *(const ulonglong2*)(sWe2 + (h * 128 + k0 + 3) * 128 + jj);
                #pragma unroll
                for (int i = 0; i < 8; i++) {
                    float4 a4 = *(const float4*)(myE1 + i * 128 + k0);
                    ull ax = pk2(a4.x), ay = pk2(a4.y), az = pk2(a4.z), aw = pk2(a4.w);
                    ffma2(acc2[i][0], ax, w0.x); ffma2(acc2[i][1], ax, w0.y);
                    ffma2(acc2[i][0], ay, w1.x); ffma2(acc2[i][1], ay, w1.y);
                    ffma2(acc2[i][0], az, w2.x); ffma2(acc2[i][1], az, w2.y);
                    ffma2(acc2[i][0], aw, w3.x); ffma2(acc2[i][1], aw, w3.y);
                }
            }
            __syncwarp();   // phase-B reads done before next-h writes
        }

        // ---- epilogue: e2 -> out + scatter + colsum (from registers) ----
        {
            float4 b = *(const float4*)(sbe2 + jj);
            #pragma unroll
            for (int i = 0; i < 8; i++) {
                float2 t0 = up2(acc2[i][0]), t1 = up2(acc2[i][1]);
                float4 r;
                r.x = fmaxf(t0.x + b.x, 0.f); r.y = fmaxf(t0.y + b.y, 0.f);
                r.z = fmaxf(t1.x + b.z, 0.f); r.w = fmaxf(t1.y + b.w, 0.f);
                *(float4*)(e2_out + (base + i) * 128 + jj) = r;
                cs2[0] += r.x; cs2[1] += r.y; cs2[2] += r.z; cs2[3] += r.w;
                int rI = __shfl_sync(0xffffffffu, idxreg, 8 + i);
                int sI = __shfl_sync(0xffffffffu, idxreg, i);
                red4(g_inc2 + (long)rI * 128 + jj, r.x, r.y, r.z, r.w);
                red4(g_out2 + (long)sI * 128 + jj, r.x, r.y, r.z, r.w);
            }
        }
    }
    red4(g_scr + OFF_E1SUM + jj,       cs1[0][0], cs1[0][1], cs1[0][2], cs1[0][3]);
    red4(g_scr + OFF_E1SUM + 128 + jj, cs1[1][0], cs1[1][1], cs1[1][2], cs1[1][3]);
    red4(g_scr + OFF_E2SUM + jj,       cs2[0], cs2[1], cs2[2], cs2[3]);
}

// ---------------- fused node kernel ----------------
// 64-node tiles, 2 CTAs/SM. GEMM1 8x8 (2k-blocked), GEMM2 8x4 (4k-blocked).
#define K2_TILES 782
__global__ void __launch_bounds__(256, 2) k_nodes(
    const float* __restrict__ nodes,
    const float* __restrict__ Wn1, const float* __restrict__ Win1,
    const float* __restrict__ Wout1, const float* __restrict__ bn1,
    const float* __restrict__ Wn2, const float* __restrict__ Win2,
    const float* __restrict__ Wout2, const float* __restrict__ bn2,
    float* __restrict__ n2_out)
{
    extern __shared__ float sm[];
    float* sN1   = sm;               // 64*256 = 16384
    float* sW    = sN1 + 16384;      // 32*256 = 8192
    float* sA    = sW + 8192;        // 64*32  = 2048
    float* sInvI = sA + 2048;        // 64
    float* sInvO = sInvI + 64;       // 64
    float* sbn1  = sInvO + 64;       // 256
    float* sbn2  = sbn1 + 256;       // 128

    const int tid = threadIdx.x;
    if (tid < 256) sbn1[tid] = bn1[tid];
    if (tid < 128) sbn2[tid] = bn2[tid];

    const int ig  = tid >> 5;        // 8 i-groups x 8 nodes (warp-uniform)
    const int jg  = tid & 31;
    const int n0  = ig * 8;
    const int jj  = jg * 8;          // GEMM1: 32 j-groups x 8 cols = 256
    const int jj2 = jg * 4;          // GEMM2: 32 j-groups x 4 cols = 128

    float csn1[8] = {0.f,0.f,0.f,0.f,0.f,0.f,0.f,0.f};
    float csn2[4] = {0.f,0.f,0.f,0.f};

    const float* g_inc1 = g_scr + OFF_INC1;
    const float* g_out1 = g_scr + OFF_OUT1;
    const float* g_inc2 = g_scr + OFF_INC2;
    const float* g_out2 = g_scr + OFF_OUT2;

    for (int tile = blockIdx.x; tile < K2_TILES; tile += gridDim.x) {
        const int base = tile * 64;
        __syncthreads();
        if (tid < 64) {
            int n = base + tid;
            sInvI[tid] = (n < NN) ? g_scr[OFF_INVIN + n]  : 0.f;
            sInvO[tid] = (n < NN) ? g_scr[OFF_INVOUT + n] : 0.f;
        }

        // ================= GEMM1: K = 544 in 17 chunks of 32 =================
        ull acc1[8][4];
        #pragma unroll
        for (int i = 0; i < 8; i++)
            #pragma unroll
            for (int q = 0; q < 4; q++) acc1[i][q] = 0ull;

        for (int c = 0; c < 17; c++) {
            __syncthreads();
            {
                const float* Wsrc; int kb;
                if (c == 0)      { Wsrc = Wn1;   kb = 0; }
                else if (c <= 8) { Wsrc = Win1;  kb = (c - 1) * 32; }
                else             { Wsrc = Wout1; kb = (c - 9) * 32; }
                #pragma unroll
                for (int r = 0; r < 8; r++) {
                    int i = tid + r * 256;
                    int k = i >> 6, j = (i & 63) * 4;
                    *(float4*)(sW + k * 256 + j) =
                        *(const float4*)(Wsrc + (long)(kb + k) * 256 + j);
                }
            }
            #pragma unroll
            for (int r = 0; r < 2; r++) {
                int i = tid + r * 256;
                int n = i >> 3, kk = (i & 7) * 4;
                int node = base + n;
                float4 v = {0.f, 0.f, 0.f, 0.f};
                if (node < NN) {
                    if (c == 0) {
                        v = *(const float4*)(nodes + (long)node * 32 + kk);
                    } else if (c <= 8) {
                        v = *(const float4*)(g_inc1 + (long)node * 256 + (c - 1) * 32 + kk);
                        float s = sInvI[n]; v.x *= s; v.y *= s; v.z *= s; v.w *= s;
                    } else {
                        v = *(const float4*)(g_out1 + (long)node * 256 + (c - 9) * 32 + kk);
                        float s = sInvO[n]; v.x *= s; v.y *= s; v.z *= s; v.w *= s;
                    }
                }
                *(float4*)(sA + n * 32 + kk) = v;
            }
            __syncthreads();
            // 2k-blocked inner loop: float2 a-loads, 16 FFMA2 per a-pair
            #pragma unroll 2
            for (int k0 = 0; k0 < 32; k0 += 2) {
                ulonglong2 wa0 = *(const ulonglong2*)(sW + k0 * 256 + jj);
                ulonglong2 wa1 = *(const ulonglong2*)(sW + k0 * 256 + jj + 4);
                ulonglong2 wb0 = *(const ulonglong2*)(sW + (k0 + 1) * 256 + jj);
                ulonglong2 wb1 = *(const ulonglong2*)(sW + (k0 + 1) * 256 + jj + 4);
                #pragma unroll
                for (int i = 0; i < 8; i++) {
                    float2 a2 = *(const float2*)(sA + (n0 + i) * 32 + k0);
                    ull ax = pk2(a2.x), ay = pk2(a2.y);
                    ffma2(acc1[i][0], ax, wa0.x);
                    ffma2(acc1[i][1], ax, wa0.y);
                    ffma2(acc1[i][2], ax, wa1.x);
                    ffma2(acc1[i][3], ax, wa1.y);
                    ffma2(acc1[i][0], ay, wb0.x);
                    ffma2(acc1[i][1], ay, wb0.y);
                    ffma2(acc1[i][2], ay, wb1.x);
                    ffma2(acc1[i][3], ay, wb1.y);
                }
            }
        }
        // epilogue: n1 -> sN1 (+colsum)
        __syncthreads();
        {
            float4 b0 = *(const float4*)(sbn1 + jj);
            float4 b1 = *(const float4*)(sbn1 + jj + 4);
            #pragma unroll
            for (int i = 0; i < 8; i++) {
                bool valid = (base + n0 + i) < NN;
                float2 t0 = up2(acc1[i][0]), t1 = up2(acc1[i][1]);
                float2 t2 = up2(acc1[i][2]), t3 = up2(acc1[i][3]);
                float4 r0, r1;
                r0.x = valid ? fmaxf(t0.x + b0.x, 0.f) : 0.f;
                r0.y = valid ? fmaxf(t0.y + b0.y, 0.f) : 0.f;
                r0.z = valid ? fmaxf(t1.x + b0.z, 0.f) : 0.f;
                r0.w = valid ? fmaxf(t1.y + b0.w, 0.f) : 0.f;
                r1.x = valid ? fmaxf(t2.x + b1.x, 0.f) : 0.f;
                r1.y = valid ? fmaxf(t2.y + b1.y, 0.f) : 0.f;
                r1.z = valid ? fmaxf(t3.x + b1.z, 0.f) : 0.f;
                r1.w = valid ? fmaxf(t3.y + b1.w, 0.f) : 0.f;
                *(float4*)(sN1 + (n0 + i) * 256 + jj)     = r0;
                *(float4*)(sN1 + (n0 + i) * 256 + jj + 4) = r1;
                csn1[0] += r0.x; csn1[1] += r0.y; csn1[2] += r0.z; csn1[3] += r0.w;
                csn1[4] += r1.x; csn1[5] += r1.y; csn1[6] += r1.z; csn1[7] += r1.w;
            }
        }

        // ================= GEMM2: K = 512 in 16 chunks of 32 =================
        ull acc2[8][2];
        #pragma unroll
        for (int i = 0; i < 8; i++) { acc2[i][0] = 0ull; acc2[i][1] = 0ull; }

        for (int c = 0; c < 16; c++) {
            __syncthreads();
            {
                const float* Wsrc; int kb;
                if (c < 8)       { Wsrc = Wn2;   kb = c * 32; }
                else if (c < 12) { Wsrc = Win2;  kb = (c - 8) * 32; }
                else             { Wsrc = Wout2; kb = (c - 12) * 32; }
                #pragma unroll
                for (int r = 0; r < 4; r++) {
                    int i = tid + r * 256;
                    int k = i >> 5, j = (i & 31) * 4;
                    *(float4*)(sW + k * 128 + j) =
                        *(const float4*)(Wsrc + (long)(kb + k) * 128 + j);
                }
            }
            if (c >= 8) {
                #pragma unroll
                for (int r = 0; r < 2; r++) {
                    int i = tid + r * 256;
                    int n = i >> 3, kk = (i & 7) * 4;
                    int node = base + n;
                    float4 v = {0.f, 0.f, 0.f, 0.f};
                    if (node < NN) {
                        if (c < 12) {
                            v = *(const float4*)(g_inc2 + (long)node * 128 + (c - 8) * 32 + kk);
                            float s = sInvI[n]; v.x *= s; v.y *= s; v.z *= s; v.w *= s;
                        } else {
                            v = *(const float4*)(g_out2 + (long)node * 128 + (c - 12) * 32 + kk);
                            float s = sInvO[n]; v.x *= s; v.y *= s; v.z *= s; v.w *= s;
                        }
                    }
                    *(float4*)(sA + n * 32 + kk) = v;
                }
            }
            __syncthreads();
            // 4k-blocked inner loops: float4 a-loads
            if (c < 8) {
                #pragma unroll 2
                for (int k0 = 0; k0 < 32; k0 += 4) {
                    ulonglong2 w0 = *(const ulonglong2*)(sW + (k0 + 0) * 128 + jj2);
                    ulonglong2 w1 = *(const ulonglong2*)(sW + (k0 + 1) * 128 + jj2);
                    ulonglong2 w2 = *(const ulonglong2*)(sW + (k0 + 2) * 128 + jj2);
                    ulonglong2 w3 = *(const ulonglong2*)(sW + (k0 + 3) * 128 + jj2);
                    #pragma unroll
                    for (int i = 0; i < 8; i++) {
                        float4 a4 = *(const float4*)(sN1 + (n0 + i) * 256 + c * 32 + k0);
                        ull ax = pk2(a4.x), ay = pk2(a4.y), az = pk2(a4.z), aw = pk2(a4.w);
                        ffma2(acc2[i][0], ax, w0.x); ffma2(acc2[i][1], ax, w0.y);
                        ffma2(acc2[i][0], ay, w1.x); ffma2(acc2[i][1], ay, w1.y);
                        ffma2(acc2[i][0], az, w2.x); ffma2(acc2[i][1], az, w2.y);
                        ffma2(acc2[i][0], aw, w3.x); ffma2(acc2[i][1], aw, w3.y);
                    }
                }
            } else {
                #pragma unroll 2
                for (int k0 = 0; k0 < 32; k0 += 4) {
                    ulonglong2 w0 = *(const ulonglong2*)(sW + (k0 + 0) * 128 + jj2);
                    ulonglong2 w1 = *(const ulonglong2*)(sW + (k0 + 1) * 128 + jj2);
                    ulonglong2 w2 = *(const ulonglong2*)(sW + (k0 + 2) * 128 + jj2);
                    ulonglong2 w3 = *(const ulonglong2*)(sW + (k0 + 3) * 128 + jj2);
                    #pragma unroll
                    for (int i = 0; i < 8; i++) {
                        float4 a4 = *(const float4*)(sA + (n0 + i) * 32 + k0);
                        ull ax = pk2(a4.x), ay = pk2(a4.y), az = pk2(a4.z), aw = pk2(a4.w);
                        ffma2(acc2[i][0], ax, w0.x); ffma2(acc2[i][1], ax, w0.y);
                        ffma2(acc2[i][0], ay, w1.x); ffma2(acc2[i][1], ay, w1.y);
                        ffma2(acc2[i][0], az, w2.x); ffma2(acc2[i][1], az, w2.y);
                        ffma2(acc2[i][0], aw, w3.x); ffma2(acc2[i][1], aw, w3.y);
                    }
                }
            }
        }
        // epilogue: n2 -> global (+colsum)
        {
            float4 b0 = *(const float4*)(sbn2 + jj2);
            #pragma unroll
            for (int i = 0; i < 8; i++) {
                int node = base + n0 + i;
                if (node < NN) {
                    float2 t0 = up2(acc2[i][0]), t1 = up2(acc2[i][1]);
                    float4 r0;
                    r0.x = fmaxf(t0.x + b0.x, 0.f);
                    r0.y = fmaxf(t0.y + b0.y, 0.f);
                    r0.z = fmaxf(t1.x + b0.z, 0.f);
                    r0.w = fmaxf(t1.y + b0.w, 0.f);
                    *(float4*)(n2_out + (long)node * 128 + jj2) = r0;
                    csn2[0] += r0.x; csn2[1] += r0.y; csn2[2] += r0.z; csn2[3] += r0.w;
                }
            }
        }
    }
    red4(g_scr + OFF_N1SUM + jj,     csn1[0], csn1[1], csn1[2], csn1[3]);
    red4(g_scr + OFF_N1SUM + jj + 4, csn1[4], csn1[5], csn1[6], csn1[7]);
    red4(g_scr + OFF_N2SUM + jj2,    csn2[0], csn2[1], csn2[2], csn2[3]);
}

// ---------------- globals kernel ----------------
__global__ void k_glob(
    const float* __restrict__ gu,
    const float* __restrict__ Wu1, const float* __restrict__ Wgn1,
    const float* __restrict__ Wge1, const float* __restrict__ bu1,
    const float* __restrict__ Wu2, const float* __restrict__ Wgn2,
    const float* __restrict__ Wge2, const float* __restrict__ bu2,
    float* __restrict__ u2_out)
{
    __shared__ float su1[256];
    __shared__ float sgu[16];
    __shared__ float sn1m[256], se1m[256];
    const int tid = threadIdx.x;
    if (tid < 16) sgu[tid] = gu[tid];
    sn1m[tid] = g_scr[OFF_N1SUM + tid] * (1.0f / NN);
    se1m[tid] = g_scr[OFF_E1SUM + tid] * (1.0f / EE);
    __syncthreads();
    {
        float s = bu1[tid];
        #pragma unroll 4
        for (int k = 0; k < 16; k++) s = fmaf(sgu[k], Wu1[k * 256 + tid], s);
        #pragma unroll 4
        for (int k = 0; k < 256; k++) {
            s = fmaf(sn1m[k], Wgn1[k * 256 + tid], s);
            s = fmaf(se1m[k], Wge1[k * 256 + tid], s);
        }
        su1[tid] = fmaxf(s, 0.f);
    }
    __syncthreads();
    if (tid < 128) {
        float s = bu2[tid];
        #pragma unroll 4
        for (int k = 0; k < 256; k++) s = fmaf(su1[k], Wu2[k * 128 + tid], s);
        #pragma unroll 4
        for (int k = 0; k < 128; k++) {
            s = fmaf(g_scr[OFF_N2SUM + k] * (1.0f / NN), Wgn2[k * 128 + tid], s);
            s = fmaf(g_scr[OFF_E2SUM + k] * (1.0f / EE), Wge2[k * 128 + tid], s);
        }
        u2_out[tid] = fmaxf(s, 0.f);
    }
}

extern "C" void kernel_launch(void* const* d_in, const int* in_sizes, int n_in,
                              void* d_out, int out_size) {
    const float* nodes = (const float*)d_in[0];
    const float* edges = (const float*)d_in[1];
    const float* gu    = (const float*)d_in[2];
    const int*   snd   = (const int*)d_in[3];
    const int*   rcv   = (const int*)d_in[4];
    const float* We1 = (const float*)d_in[5];
    const float* be1 = (const float*)d_in[6];
    const float* Wn1 = (const float*)d_in[7];
    const float* Win1 = (const float*)d_in[8];
    const float* Wout1 = (const float*)d_in[9];
    const float* bn1 = (const float*)d_in[10];
    const float* Wu1 = (const float*)d_in[11];
    const float* Wgn1 = (const float*)d_in[12];
    const float* Wge1 = (const float*)d_in[13];
    const float* bu1 = (const float*)d_in[14];
    const float* We2 = (const float*)d_in[15];
    const float* be2 = (const float*)d_in[16];
    const float* Wn2 = (const float*)d_in[17];
    const float* Win2 = (const float*)d_in[18];
    const float* Wout2 = (const float*)d_in[19];
    const float* bn2 = (const float*)d_in[20];
    const float* Wu2 = (const float*)d_in[21];
    const float* Wgn2 = (const float*)d_in[22];
    const float* Wge2 = (const float*)d_in[23];
    const float* bu2 = (const float*)d_in[24];

    float* out    = (float*)d_out;
    float* n2_out = out;
    float* e2_out = out + (long)NN * H2;                       // 6,400,000
    float* u2_out = out + (long)NN * H2 + (long)EE * H2;       // 57,600,000

    const int SMEM_K1 = (32768 + 4096 + 16384 + 2048 + 256 + 128) * 4;   // 222720
    const int SMEM_K2 = (16384 + 8192 + 2048 + 64 + 64 + 256 + 128) * 4; // 108544
    cudaFuncSetAttribute(k_edges, cudaFuncAttributeMaxDynamicSharedMemorySize, SMEM_K1);
    cudaFuncSetAttribute(k_nodes, cudaFuncAttributeMaxDynamicSharedMemorySize, SMEM_K2);

    k_zero<<<(ZERO_FLOATS / 4 + 255) / 256, 256>>>();
    k_deg<<<(EE + 255) / 256, 256>>>(snd, rcv);
    k_inv<<<(NN + 255) / 256, 256>>>();
    k_edges<<<148, 512, SMEM_K1>>>(edges, snd, rcv, We1, be1, We2, be2, e2_out);
    k_nodes<<<296, 256, SMEM_K2>>>(nodes, Wn1, Win1, Wout1, bn1,
                                   Wn2, Win2, Wout2, bn2, n2_out);
    k_glob<<<1, 256>>>(gu, Wu1, Wgn1, Wge1, bu1, Wu2, Wgn2, Wge2, bu2, u2_out);
}

// round 6
// speedup vs baseline: 1.0438x; 1.0438x over previous
#include <cuda_runtime.h>
#include <cstdint>

#define NN 50000
#define EE 400000
#define H1 256
#define H2 128

// ---- scratch layout (floats) ----
#define OFF_INC1   0                       // N*256
#define OFF_OUT1   12800000                // N*256
#define OFF_INC2   25600000                // N*128
#define OFF_OUT2   32000000                // N*128
#define OFF_E1SUM  38400000                // 256
#define OFF_E2SUM  38400256                // 128
#define OFF_N1SUM  38400384                // 256
#define OFF_N2SUM  38400640                // 128
#define OFF_INVIN  38400768                // N
#define OFF_INVOUT 38450768                // N
#define SCR_TOTAL  38500864
#define ZERO_FLOATS 38400768               // [0, OFF_INVIN) must be zeroed

__device__ float g_scr[SCR_TOTAL];
__device__ int   g_cnt[2 * NN];

typedef unsigned long long ull;

__device__ __forceinline__ void red4(float* p, float a, float b, float c, float d) {
    asm volatile("red.global.add.v4.f32 [%0], {%1,%2,%3,%4};"
                 :: "l"(p), "f"(a), "f"(b), "f"(c), "f"(d) : "memory");
}
__device__ __forceinline__ ull pk2(float x) {
    ull r; asm("mov.b64 %0, {%1, %1};" : "=l"(r) : "f"(x)); return r;
}
__device__ __forceinline__ void ffma2(ull& acc, ull a, ull b) {
    asm("fma.rn.f32x2 %0, %1, %2, %0;" : "+l"(acc) : "l"(a), "l"(b));
}
__device__ __forceinline__ float2 up2(ull v) {
    float2 f; asm("mov.b64 {%0, %1}, %2;" : "=f"(f.x), "=f"(f.y) : "l"(v)); return f;
}

// ---------------- zero scratch ----------------
__global__ void k_zero() {
    long i = (long)blockIdx.x * 256 + threadIdx.x;
    if (i < ZERO_FLOATS / 4) {
        float4 z = {0.f, 0.f, 0.f, 0.f};
        *(float4*)(g_scr + i * 4) = z;
    }
    if (i < (2 * NN) / 4) {
        int4 z = {0, 0, 0, 0};
        *(int4*)(g_cnt + i * 4) = z;
    }
}

// ---------------- degrees ----------------
__global__ void k_deg(const int* __restrict__ snd, const int* __restrict__ rcv) {
    int i = blockIdx.x * 256 + threadIdx.x;
    if (i < EE) {
        atomicAdd(&g_cnt[rcv[i]], 1);
        atomicAdd(&g_cnt[NN + snd[i]], 1);
    }
}

__global__ void k_inv() {
    int i = blockIdx.x * 256 + threadIdx.x;
    if (i < NN) {
        int ci = g_cnt[i];      g_scr[OFF_INVIN  + i] = 1.0f / (float)(ci > 1 ? ci : 1);
        int co = g_cnt[NN + i]; g_scr[OFF_INVOUT + i] = 1.0f / (float)(co > 1 ? co : 1);
    }
}

// ---------------- fused edge kernel (warp-autonomous, 12 warps) ----------------
// 384 threads = 12 warps -> 170 regs/thread for deep software pipelining.
// Each warp owns 8 edges/group; a-loads are warp broadcasts; no __syncthreads
// in the main loop. Per thread: 8 edges x 4 cols.
#define GRPS 50000   /* EE / 8 */
#define NWARP 12
#define NT 384
__global__ void __launch_bounds__(NT, 1) k_edges(
    const float* __restrict__ edges, const int* __restrict__ snd, const int* __restrict__ rcv,
    const float* __restrict__ We1, const float* __restrict__ be1,
    const float* __restrict__ We2, const float* __restrict__ be2,
    float* __restrict__ e2_out)
{
    extern __shared__ float sm[];
    float* sWe2 = sm;                 // 256*128 = 32768
    float* sWe1 = sWe2 + 32768;       // 16*256  = 4096
    float* sE1  = sWe1 + 4096;        // 12 warps * 8*128 = 12288
    float* sX   = sE1 + 12288;        // 12 warps * 8*16  = 1536
    float* sbe1 = sX + 1536;          // 256
    float* sbe2 = sbe1 + 256;         // 128

    const int tid = threadIdx.x;
    for (int i = tid; i < 32768; i += NT) sWe2[i] = We2[i];
    for (int i = tid; i < 4096;  i += NT) sWe1[i] = We1[i];
    if (tid < 256) sbe1[tid] = be1[tid];
    else           sbe2[tid - 256] = be2[tid - 256];
    __syncthreads();

    const int wid  = tid >> 5;
    const int lane = tid & 31;
    float* myE1 = sE1 + wid * 1024;   // 8 rows x 128
    float* myX  = sX  + wid * 128;    // 8 rows x 16
    const int jj = lane * 4;

    float cs1[2][4] = {{0.f,0.f,0.f,0.f},{0.f,0.f,0.f,0.f}};
    float cs2[4] = {0.f,0.f,0.f,0.f};

    float* g_inc1 = g_scr + OFF_INC1;
    float* g_out1 = g_scr + OFF_OUT1;
    float* g_inc2 = g_scr + OFF_INC2;
    float* g_out2 = g_scr + OFF_OUT2;

    const int le = lane >> 2, lq = lane & 3;   // X fill mapping

    for (int grp = blockIdx.x * NWARP + wid; grp < GRPS; grp += gridDim.x * NWARP) {
        const long base = (long)grp * 8;
        __syncwarp();   // myX/myE1 free of previous-group readers
        // ---- fill X (8 edges x 16) + indices in lanes ----
        *(float4*)(myX + le * 16 + lq * 4) =
            *(const float4*)(edges + (base + le) * 16 + lq * 4);
        int idxreg = 0;
        if (lane < 8)       idxreg = snd[base + lane];
        else if (lane < 16) idxreg = rcv[base + lane - 8];
        __syncwarp();

        ull acc2[8][2];
        #pragma unroll
        for (int i = 0; i < 8; i++) { acc2[i][0] = 0ull; acc2[i][1] = 0ull; }

        #pragma unroll
        for (int h = 0; h < 2; h++) {
            // ---- phase A: e1[:, h*128+jj .. +3] for all 8 rows ----
            ull accA[8][2];
            #pragma unroll
            for (int i = 0; i < 8; i++) { accA[i][0] = 0ull; accA[i][1] = 0ull; }
            #pragma unroll
            for (int k0 = 0; k0 < 16; k0 += 4) {
                ulonglong2 w0 = *(const ulonglong2*)(sWe1 + (k0 + 0) * 256 + h * 128 + jj);
                ulonglong2 w1 = *(const ulonglong2*)(sWe1 + (k0 + 1) * 256 + h * 128 + jj);
                ulonglong2 w2 = *(const ulonglong2*)(sWe1 + (k0 + 2) * 256 + h * 128 + jj);
                ulonglong2 w3 = *(const ulonglong2*)(sWe1 + (k0 + 3) * 256 + h * 128 + jj);
                #pragma unroll
                for (int i = 0; i < 8; i++) {
                    float4 a4 = *(const float4*)(myX + i * 16 + k0);
                    ull ax = pk2(a4.x), ay = pk2(a4.y), az = pk2(a4.z), aw = pk2(a4.w);
                    ffma2(accA[i][0], ax, w0.x); ffma2(accA[i][1], ax, w0.y);
                    ffma2(accA[i][0], ay, w1.x); ffma2(accA[i][1], ay, w1.y);
                    ffma2(accA[i][0], az, w2.x); ffma2(accA[i][1], az, w2.y);
                    ffma2(accA[i][0], aw, w3.x); ffma2(accA[i][1], aw, w3.y);
                }
            }
            // relu+bias -> store to myE1 + scatter from registers
            {
                float4 b = *(const float4*)(sbe1 + h * 128 + jj);
                #pragma unroll
                for (int i = 0; i < 8; i++) {
                    float2 t0 = up2(accA[i][0]), t1 = up2(accA[i][1]);
                    float4 r;
                    r.x = fmaxf(t0.x + b.x, 0.f); r.y = fmaxf(t0.y + b.y, 0.f);
                    r.z = fmaxf(t1.x + b.z, 0.f); r.w = fmaxf(t1.y + b.w, 0.f);
                    *(float4*)(myE1 + i * 128 + jj) = r;
                    cs1[h][0] += r.x; cs1[h][1] += r.y; cs1[h][2] += r.z; cs1[h][3] += r.w;
                    int rI = __shfl_sync(0xffffffffu, idxreg, 8 + i);
                    int sI = __shfl_sync(0xffffffffu, idxreg, i);
                    red4(g_inc1 + (long)rI * 256 + h * 128 + jj, r.x, r.y, r.z, r.w);
                    red4(g_out1 + (long)sI * 256 + h * 128 + jj, r.x, r.y, r.z, r.w);
                }
            }
            __syncwarp();   // myE1 complete before cross-lane reads

            // ---- phase B: acc2 += e1_half @ We2[h*128.., jj..jj+3] ----
            #pragma unroll 4
            for (int k0 = 0; k0 < 128; k0 += 4) {
                ulonglong2 w0 = *(const ulonglong2*)(sWe2 + (h * 128 + k0 + 0) * 128 + jj);
                ulonglong2 w1 = *(const ulonglong2*)(sWe2 + (h * 128 + k0 + 1) * 128 + jj);
                ulonglong2 w2 = *(const ulonglong2*)(sWe2 + (h * 128 + k0 + 2) * 128 + jj);
                ulonglong2 w3 = *(const ulonglong2*)(sWe2 + (h * 128 + k0 + 3) * 128 + jj);
                #pragma unroll
                for (int i = 0; i < 8; i++) {
                    float4 a4 = *(const float4*)(myE1 + i * 128 + k0);
                    ull ax = pk2(a4.x), ay = pk2(a4.y), az = pk2(a4.z), aw = pk2(a4.w);
                    ffma2(acc2[i][0], ax, w0.x); ffma2(acc2[i][1], ax, w0.y);
                    ffma2(acc2[i][0], ay, w1.x); ffma2(acc2[i][1], ay, w1.y);
                    ffma2(acc2[i][0], az, w2.x); ffma2(acc2[i][1], az, w2.y);
                    ffma2(acc2[i][0], aw, w3.x); ffma2(acc2[i][1], aw, w3.y);
                }
            }
            __syncwarp();   // phase-B reads done before next-h writes
        }

        // ---- epilogue: e2 -> out + scatter + colsum (from registers) ----
        {
            float4 b = *(const float4*)(sbe2 + jj);
            #pragma unroll
            for (int i = 0; i < 8; i++) {
                float2 t0 = up2(acc2[i][0]), t1 = up2(acc2[i][1]);
                float4 r;
                r.x = fmaxf(t0.x + b.x, 0.f); r.y = fmaxf(t0.y + b.y, 0.f);
                r.z = fmaxf(t1.x + b.z, 0.f); r.w = fmaxf(t1.y + b.w, 0.f);
                *(float4*)(e2_out + (base + i) * 128 + jj) = r;
                cs2[0] += r.x; cs2[1] += r.y; cs2[2] += r.z; cs2[3] += r.w;
                int rI = __shfl_sync(0xffffffffu, idxreg, 8 + i);
                int sI = __shfl_sync(0xffffffffu, idxreg, i);
                red4(g_inc2 + (long)rI * 128 + jj, r.x, r.y, r.z, r.w);
                red4(g_out2 + (long)sI * 128 + jj, r.x, r.y, r.z, r.w);
            }
        }
    }
    red4(g_scr + OFF_E1SUM + jj,       cs1[0][0], cs1[0][1], cs1[0][2], cs1[0][3]);
    red4(g_scr + OFF_E1SUM + 128 + jj, cs1[1][0], cs1[1][1], cs1[1][2], cs1[1][3]);
    red4(g_scr + OFF_E2SUM + jj,       cs2[0], cs2[1], cs2[2], cs2[3]);
}

// ---------------- fused node kernel (round-4 version, verbatim) ----------------
// 64-node tiles, 2 CTAs/SM. GEMM1 8x8 tiles, GEMM2 8x4 tiles, f32x2 FMAs.
#define K2_TILES 782
__global__ void __launch_bounds__(256, 2) k_nodes(
    const float* __restrict__ nodes,
    const float* __restrict__ Wn1, const float* __restrict__ Win1,
    const float* __restrict__ Wout1, const float* __restrict__ bn1,
    const float* __restrict__ Wn2, const float* __restrict__ Win2,
    const float* __restrict__ Wout2, const float* __restrict__ bn2,
    float* __restrict__ n2_out)
{
    extern __shared__ float sm[];
    float* sN1   = sm;               // 64*256 = 16384
    float* sW    = sN1 + 16384;      // 32*256 = 8192
    float* sA    = sW + 8192;        // 64*32  = 2048
    float* sInvI = sA + 2048;        // 64
    float* sInvO = sInvI + 64;       // 64
    float* sbn1  = sInvO + 64;       // 256
    float* sbn2  = sbn1 + 256;       // 128

    const int tid = threadIdx.x;
    if (tid < 256) sbn1[tid] = bn1[tid];
    if (tid < 128) sbn2[tid] = bn2[tid];

    const int ig  = tid >> 5;        // 8 i-groups x 8 nodes (warp-uniform)
    const int jg  = tid & 31;
    const int n0  = ig * 8;
    const int jj  = jg * 8;          // GEMM1: 32 j-groups x 8 cols = 256
    const int jj2 = jg * 4;          // GEMM2: 32 j-groups x 4 cols = 128

    float csn1[8] = {0.f,0.f,0.f,0.f,0.f,0.f,0.f,0.f};
    float csn2[4] = {0.f,0.f,0.f,0.f};

    const float* g_inc1 = g_scr + OFF_INC1;
    const float* g_out1 = g_scr + OFF_OUT1;
    const float* g_inc2 = g_scr + OFF_INC2;
    const float* g_out2 = g_scr + OFF_OUT2;

    for (int tile = blockIdx.x; tile < K2_TILES; tile += gridDim.x) {
        const int base = tile * 64;
        __syncthreads();
        if (tid < 64) {
            int n = base + tid;
            sInvI[tid] = (n < NN) ? g_scr[OFF_INVIN + n]  : 0.f;
            sInvO[tid] = (n < NN) ? g_scr[OFF_INVOUT + n] : 0.f;
        }

        // ================= GEMM1: K = 544 in 17 chunks of 32 =================
        ull acc1[8][4];
        #pragma unroll
        for (int i = 0; i < 8; i++)
            #pragma unroll
            for (int q = 0; q < 4; q++) acc1[i][q] = 0ull;

        for (int c = 0; c < 17; c++) {
            __syncthreads();
            {
                const float* Wsrc; int kb;
                if (c == 0)      { Wsrc = Wn1;   kb = 0; }
                else if (c <= 8) { Wsrc = Win1;  kb = (c - 1) * 32; }
                else             { Wsrc = Wout1; kb = (c - 9) * 32; }
                #pragma unroll
                for (int r = 0; r < 8; r++) {
                    int i = tid + r * 256;
                    int k = i >> 6, j = (i & 63) * 4;
                    *(float4*)(sW + k * 256 + j) =
                        *(const float4*)(Wsrc + (long)(kb + k) * 256 + j);
                }
            }
            #pragma unroll
            for (int r = 0; r < 2; r++) {
                int i = tid + r * 256;
                int n = i >> 3, kk = (i & 7) * 4;
                int node = base + n;
                float4 v = {0.f, 0.f, 0.f, 0.f};
                if (node < NN) {
                    if (c == 0) {
                        v = *(const float4*)(nodes + (long)node * 32 + kk);
                    } else if (c <= 8) {
                        v = *(const float4*)(g_inc1 + (long)node * 256 + (c - 1) * 32 + kk);
                        float s = sInvI[n]; v.x *= s; v.y *= s; v.z *= s; v.w *= s;
                    } else {
                        v = *(const float4*)(g_out1 + (long)node * 256 + (c - 9) * 32 + kk);
                        float s = sInvO[n]; v.x *= s; v.y *= s; v.z *= s; v.w *= s;
                    }
                }
                *(float4*)(sA + n * 32 + kk) = v;
            }
            __syncthreads();
            #pragma unroll 4
            for (int k = 0; k < 32; k++) {
                ulonglong2 w01 = *(const ulonglong2*)(sW + k * 256 + jj);
                ulonglong2 w23 = *(const ulonglong2*)(sW + k * 256 + jj + 4);
                #pragma unroll
                for (int i = 0; i < 8; i++) {
                    ull a = pk2(sA[(n0 + i) * 32 + k]);
                    ffma2(acc1[i][0], a, w01.x);
                    ffma2(acc1[i][1], a, w01.y);
                    ffma2(acc1[i][2], a, w23.x);
                    ffma2(acc1[i][3], a, w23.y);
                }
            }
        }
        // epilogue: n1 -> sN1 (+colsum)
        __syncthreads();
        {
            float4 b0 = *(const float4*)(sbn1 + jj);
            float4 b1 = *(const float4*)(sbn1 + jj + 4);
            #pragma unroll
            for (int i = 0; i < 8; i++) {
                bool valid = (base + n0 + i) < NN;
                float2 t0 = up2(acc1[i][0]), t1 = up2(acc1[i][1]);
                float2 t2 = up2(acc1[i][2]), t3 = up2(acc1[i][3]);
                float4 r0, r1;
                r0.x = valid ? fmaxf(t0.x + b0.x, 0.f) : 0.f;
                r0.y = valid ? fmaxf(t0.y + b0.y, 0.f) : 0.f;
                r0.z = valid ? fmaxf(t1.x + b0.z, 0.f) : 0.f;
                r0.w = valid ? fmaxf(t1.y + b0.w, 0.f) : 0.f;
                r1.x = valid ? fmaxf(t2.x + b1.x, 0.f) : 0.f;
                r1.y = valid ? fmaxf(t2.y + b1.y, 0.f) : 0.f;
                r1.z = valid ? fmaxf(t3.x + b1.z, 0.f) : 0.f;
                r1.w = valid ? fmaxf(t3.y + b1.w, 0.f) : 0.f;
                *(float4*)(sN1 + (n0 + i) * 256 + jj)     = r0;
                *(float4*)(sN1 + (n0 + i) * 256 + jj + 4) = r1;
                csn1[0] += r0.x; csn1[1] += r0.y; csn1[2] += r0.z; csn1[3] += r0.w;
                csn1[4] += r1.x; csn1[5] += r1.y; csn1[6] += r1.z; csn1[7] += r1.w;
            }
        }

        // ================= GEMM2: K = 512 in 16 chunks of 32 =================
        ull acc2[8][2];
        #pragma unroll
        for (int i = 0; i < 8; i++) { acc2[i][0] = 0ull; acc2[i][1] = 0ull; }

        for (int c = 0; c < 16; c++) {
            __syncthreads();
            {
                const float* Wsrc; int kb;
                if (c < 8)       { Wsrc = Wn2;   kb = c * 32; }
                else if (c < 12) { Wsrc = Win2;  kb = (c - 8) * 32; }
                else             { Wsrc = Wout2; kb = (c - 12) * 32; }
                #pragma unroll
                for (int r = 0; r < 4; r++) {
                    int i = tid + r * 256;
                    int k = i >> 5, j = (i & 31) * 4;
                    *(float4*)(sW + k * 128 + j) =
                        *(const float4*)(Wsrc + (long)(kb + k) * 128 + j);
                }
            }
            if (c >= 8) {
                #pragma unroll
                for (int r = 0; r < 2; r++) {
                    int i = tid + r * 256;
                    int n = i >> 3, kk = (i & 7) * 4;
                    int node = base + n;
                    float4 v = {0.f, 0.f, 0.f, 0.f};
                    if (node < NN) {
                        if (c < 12) {
                            v = *(const float4*)(g_inc2 + (long)node * 128 + (c - 8) * 32 + kk);
                            float s = sInvI[n]; v.x *= s; v.y *= s; v.z *= s; v.w *= s;
                        } else {
                            v = *(const float4*)(g_out2 + (long)node * 128 + (c - 12) * 32 + kk);
                            float s = sInvO[n]; v.x *= s; v.y *= s; v.z *= s; v.w *= s;
                        }
                    }
                    *(float4*)(sA + n * 32 + kk) = v;
                }
            }
            __syncthreads();
            if (c < 8) {
                #pragma unroll 4
                for (int k = 0; k < 32; k++) {
                    ulonglong2 w = *(const ulonglong2*)(sW + k * 128 + jj2);
                    #pragma unroll
                    for (int i = 0; i < 8; i++) {
                        ull a = pk2(sN1[(n0 + i) * 256 + c * 32 + k]);
                        ffma2(acc2[i][0], a, w.x);
                        ffma2(acc2[i][1], a, w.y);
                    }
                }
            } else {
                #pragma unroll 4
                for (int k = 0; k < 32; k++) {
                    ulonglong2 w = *(const ulonglong2*)(sW + k * 128 + jj2);
                    #pragma unroll
                    for (int i = 0; i < 8; i++) {
                        ull a = pk2(sA[(n0 + i) * 32 + k]);
                        ffma2(acc2[i][0], a, w.x);
                        ffma2(acc2[i][1], a, w.y);
                    }
                }
            }
        }
        // epilogue: n2 -> global (+colsum)
        {
            float4 b0 = *(const float4*)(sbn2 + jj2);
            #pragma unroll
            for (int i = 0; i < 8; i++) {
                int node = base + n0 + i;
                if (node < NN) {
                    float2 t0 = up2(acc2[i][0]), t1 = up2(acc2[i][1]);
                    float4 r0;
                    r0.x = fmaxf(t0.x + b0.x, 0.f);
                    r0.y = fmaxf(t0.y + b0.y, 0.f);
                    r0.z = fmaxf(t1.x + b0.z, 0.f);
                    r0.w = fmaxf(t1.y + b0.w, 0.f);
                    *(float4*)(n2_out + (long)node * 128 + jj2) = r0;
                    csn2[0] += r0.x; csn2[1] += r0.y; csn2[2] += r0.z; csn2[3] += r0.w;
                }
            }
        }
    }
    red4(g_scr + OFF_N1SUM + jj,     csn1[0], csn1[1], csn1[2], csn1[3]);
    red4(g_scr + OFF_N1SUM + jj + 4, csn1[4], csn1[5], csn1[6], csn1[7]);
    red4(g_scr + OFF_N2SUM + jj2,    csn2[0], csn2[1], csn2[2], csn2[3]);
}

// ---------------- globals kernel ----------------
__global__ void k_glob(
    const float* __restrict__ gu,
    const float* __restrict__ Wu1, const float* __restrict__ Wgn1,
    const float* __restrict__ Wge1, const float* __restrict__ bu1,
    const float* __restrict__ Wu2, const float* __restrict__ Wgn2,
    const float* __restrict__ Wge2, const float* __restrict__ bu2,
    float* __restrict__ u2_out)
{
    __shared__ float su1[256];
    __shared__ float sgu[16];
    __shared__ float sn1m[256], se1m[256];
    const int tid = threadIdx.x;
    if (tid < 16) sgu[tid] = gu[tid];
    sn1m[tid] = g_scr[OFF_N1SUM + tid] * (1.0f / NN);
    se1m[tid] = g_scr[OFF_E1SUM + tid] * (1.0f / EE);
    __syncthreads();
    {
        float s = bu1[tid];
        #pragma unroll 4
        for (int k = 0; k < 16; k++) s = fmaf(sgu[k], Wu1[k * 256 + tid], s);
        #pragma unroll 4
        for (int k = 0; k < 256; k++) {
            s = fmaf(sn1m[k], Wgn1[k * 256 + tid], s);
            s = fmaf(se1m[k], Wge1[k * 256 + tid], s);
        }
        su1[tid] = fmaxf(s, 0.f);
    }
    __syncthreads();
    if (tid < 128) {
        float s = bu2[tid];
        #pragma unroll 4
        for (int k = 0; k < 256; k++) s = fmaf(su1[k], Wu2[k * 128 + tid], s);
        #pragma unroll 4
        for (int k = 0; k < 128; k++) {
            s = fmaf(g_scr[OFF_N2SUM + k] * (1.0f / NN), Wgn2[k * 128 + tid], s);
            s = fmaf(g_scr[OFF_E2SUM + k] * (1.0f / EE), Wge2[k * 128 + tid], s);
        }
        u2_out[tid] = fmaxf(s, 0.f);
    }
}

extern "C" void kernel_launch(void* const* d_in, const int* in_sizes, int n_in,
                              void* d_out, int out_size) {
    const float* nodes = (const float*)d_in[0];
    const float* edges = (const float*)d_in[1];
    const float* gu    = (const float*)d_in[2];
    const int*   snd   = (const int*)d_in[3];
    const int*   rcv   = (const int*)d_in[4];
    const float* We1 = (const float*)d_in[5];
    const float* be1 = (const float*)d_in[6];
    const float* Wn1 = (const float*)d_in[7];
    const float* Win1 = (const float*)d_in[8];
    const float* Wout1 = (const float*)d_in[9];
    const float* bn1 = (const float*)d_in[10];
    const float* Wu1 = (const float*)d_in[11];
    const float* Wgn1 = (const float*)d_in[12];
    const float* Wge1 = (const float*)d_in[13];
    const float* bu1 = (const float*)d_in[14];
    const float* We2 = (const float*)d_in[15];
    const float* be2 = (const float*)d_in[16];
    const float* Wn2 = (const float*)d_in[17];
    const float* Win2 = (const float*)d_in[18];
    const float* Wout2 = (const float*)d_in[19];
    const float* bn2 = (const float*)d_in[20];
    const float* Wu2 = (const float*)d_in[21];
    const float* Wgn2 = (const float*)d_in[22];
    const float* Wge2 = (const float*)d_in[23];
    const float* bu2 = (const float*)d_in[24];

    float* out    = (float*)d_out;
    float* n2_out = out;
    float* e2_out = out + (long)NN * H2;                       // 6,400,000
    float* u2_out = out + (long)NN * H2 + (long)EE * H2;       // 57,600,000

    const int SMEM_K1 = (32768 + 4096 + 12288 + 1536 + 256 + 128) * 4;   // 204288
    const int SMEM_K2 = (16384 + 8192 + 2048 + 64 + 64 + 256 + 128) * 4; // 108544
    cudaFuncSetAttribute(k_edges, cudaFuncAttributeMaxDynamicSharedMemorySize, SMEM_K1);
    cudaFuncSetAttribute(k_nodes, cudaFuncAttributeMaxDynamicSharedMemorySize, SMEM_K2);

    k_zero<<<(ZERO_FLOATS / 4 + 255) / 256, 256>>>();
    k_deg<<<(EE + 255) / 256, 256>>>(snd, rcv);
    k_inv<<<(NN + 255) / 256, 256>>>();
    k_edges<<<148, NT, SMEM_K1>>>(edges, snd, rcv, We1, be1, We2, be2, e2_out);
    k_nodes<<<296, 256, SMEM_K2>>>(nodes, Wn1, Win1, Wout1, bn1,
                                   Wn2, Win2, Wout2, bn2, n2_out);
    k_glob<<<1, 256>>>(gu, Wu1, Wgn1, Wge1, bu1, Wu2, Wgn2, Wge2, bu2, u2_out);
}